// round 12
// baseline (speedup 1.0000x reference)
#include <cuda_runtime.h>
#include <math.h>
#include <stdint.h>

constexpr int Bc=4, Sc=512, Dc=512, Ic=1024, Cc=32, NCc=16;
constexpr long long SD=(long long)Sc*Dc;
constexpr long long ID=(long long)Ic*Dc;
constexpr long long CI=(long long)Cc*Ic;
constexpr long long CD=(long long)Cc*Dc;
constexpr long long SI=(long long)Sc*Ic;

// ---------------- persistent device scratch ----------------
__device__ float g_k[Bc*Sc*Dc];
__device__ float g_v[Bc*Sc*Dc];
__device__ float g_q[Bc*Sc*Dc];
__device__ float g_theta[Bc*Sc];
__device__ float g_alpha[Bc*Sc];
__device__ float g_eta[Bc*Sc];
__device__ float g_MW1[Bc*Ic*Dc];
__device__ float g_SW1[Bc*Ic*Dc];
__device__ float g_MW2[Bc*Dc*Ic];
__device__ float g_SW2[Bc*Dc*Ic];
__device__ float g_Mln[Bc*Dc];
__device__ float g_Sln[Bc*Dc];
__device__ float g_z[Bc*Cc*Ic];
__device__ float g_h[Bc*Cc*Ic];
__device__ float g_op[2*Bc*Cc*Dc];
__device__ float g_do[Bc*Cc*Dc];
__device__ float g_gln[Bc*Cc*Dc];
__device__ float g_p[Bc*Cc*Ic];
__device__ float g_npp[Bc*Cc*32];
__device__ float g_nk[Bc*Cc], g_ndo[Bc*Cc], g_ngl[Bc*Cc], g_nh[Bc*Cc];
__device__ float g_sE[Bc*Cc], g_sc2[Bc*Cc];
__device__ float g_Ab[Bc], g_Bpb[Bc], g_cSb[Bc];
__device__ float g_hbuf[Bc*Sc*Ic];
__device__ float g_obuf[Bc*Sc*Dc];
__device__ int g_barCount;
__device__ int g_barGen;

__device__ __forceinline__ float sigmoidf(float v){ return 1.f/(1.f+expf(-v)); }

// ---------------- packed f32x2 primitives ----------------
typedef unsigned long long ull;

__device__ __forceinline__ ull pack2(float x, float y){
    ull r;
    asm("mov.b64 %0, {%1, %2};" : "=l"(r) : "r"(__float_as_uint(x)), "r"(__float_as_uint(y)));
    return r;
}
__device__ __forceinline__ void unpack2(ull v, float& x, float& y){
    unsigned int a, b;
    asm("mov.b64 {%0, %1}, %2;" : "=r"(a), "=r"(b) : "l"(v));
    x = __uint_as_float(a); y = __uint_as_float(b);
}
__device__ __forceinline__ ull ffma2(ull a, ull b, ull c){
    ull d;
    asm("fma.rn.f32x2 %0, %1, %2, %3;" : "=l"(d) : "l"(a), "l"(b), "l"(c));
    return d;
}

__device__ __forceinline__ float blockReduce(float v){
    __shared__ float sred[33];
    int lane = threadIdx.x & 31, w = threadIdx.x >> 5;
    #pragma unroll
    for(int o=16;o>0;o>>=1) v += __shfl_down_sync(0xffffffffu, v, o);
    if(lane==0) sred[w] = v;
    __syncthreads();
    int nw = (blockDim.x + 31) >> 5;
    if(w==0){
        float r = (lane < nw) ? sred[lane] : 0.f;
        #pragma unroll
        for(int o=16;o>0;o>>=1) r += __shfl_down_sync(0xffffffffu, r, o);
        if(lane==0) sred[32] = r;
    }
    __syncthreads();
    float r = sred[32];
    __syncthreads();
    return r;
}

// ---------------- grid barrier (all blocks resident: grid = #SMs, 1 block/SM) ----------------
__device__ __forceinline__ void gridSync(int nb){
    __syncthreads();
    if(threadIdx.x==0){
        int gen = *((volatile int*)&g_barGen);
        __threadfence();
        if(atomicAdd(&g_barCount, 1) == nb-1){
            g_barCount = 0;
            __threadfence();
            atomicExch(&g_barGen, gen+1);
        } else {
            while(*((volatile int*)&g_barGen) == gen){ __nanosleep(40); }
            __threadfence();
        }
    }
    __syncthreads();
}

// ---------------- init ----------------
__global__ void init_kernel(const float* __restrict__ w1, const float* __restrict__ w2,
                            const float* __restrict__ lnw){
    int idx = blockIdx.x*256 + threadIdx.x;
    float a = w1[idx], b2 = w2[idx];
    #pragma unroll
    for(int b=0;b<Bc;b++){
        g_MW1[b*Ic*Dc + idx] = a;   g_SW1[b*Ic*Dc + idx] = 0.f;
        g_MW2[b*Dc*Ic + idx] = b2;  g_SW2[b*Dc*Ic + idx] = 0.f;
    }
    if(idx < Dc){
        float l = lnw[idx];
        #pragma unroll
        for(int b=0;b<Bc;b++){ g_Mln[b*Dc+idx] = l; g_Sln[b*Dc+idx] = 0.f; }
    }
}

// ---------------- 128x128 NT tile, 256 threads, FFMA2 (projections + retrieval) ----------------
__device__ __forceinline__ void dev_gemm128(
    const float* __restrict__ Ab, int lda,
    const float* __restrict__ Bb, int ldb,
    float* __restrict__ Cb, int ldc,
    int K, int mode)
{
    __shared__ float As[16*132];
    __shared__ float Bs[16*132];
    const int tid = threadIdx.x;
    const int ty = tid>>4, tx = tid&15;
    ull acc2[8][4];
    #pragma unroll
    for(int i=0;i<8;i++){
        #pragma unroll
        for(int j=0;j<4;j++) acc2[i][j] = 0ull;
    }
    const int lf = tid*2;
    const int m0 = lf>>2,     ka0 = (lf&3)*4;
    const int m1 = (lf+1)>>2, ka1 = ((lf+1)&3)*4;
    for(int k0=0;k0<K;k0+=16){
        float4 a0 = *(const float4*)&Ab[(long long)m0*lda + k0 + ka0];
        float4 a1 = *(const float4*)&Ab[(long long)m1*lda + k0 + ka1];
        float4 b0 = *(const float4*)&Bb[(long long)m0*ldb + k0 + ka0];
        float4 b1 = *(const float4*)&Bb[(long long)m1*ldb + k0 + ka1];
        As[(ka0+0)*132+m0]=a0.x; As[(ka0+1)*132+m0]=a0.y; As[(ka0+2)*132+m0]=a0.z; As[(ka0+3)*132+m0]=a0.w;
        As[(ka1+0)*132+m1]=a1.x; As[(ka1+1)*132+m1]=a1.y; As[(ka1+2)*132+m1]=a1.z; As[(ka1+3)*132+m1]=a1.w;
        Bs[(ka0+0)*132+m0]=b0.x; Bs[(ka0+1)*132+m0]=b0.y; Bs[(ka0+2)*132+m0]=b0.z; Bs[(ka0+3)*132+m0]=b0.w;
        Bs[(ka1+0)*132+m1]=b1.x; Bs[(ka1+1)*132+m1]=b1.y; Bs[(ka1+2)*132+m1]=b1.z; Bs[(ka1+3)*132+m1]=b1.w;
        __syncthreads();
        #pragma unroll
        for(int kk=0;kk<16;kk++){
            float4 av0 = *(float4*)&As[kk*132 + ty*4];
            float4 av1 = *(float4*)&As[kk*132 + 64 + ty*4];
            ulonglong2 bq0 = *(ulonglong2*)&Bs[kk*132 + tx*4];
            ulonglong2 bq1 = *(ulonglong2*)&Bs[kk*132 + 64 + tx*4];
            ull bp[4] = {bq0.x, bq0.y, bq1.x, bq1.y};
            float av[8] = {av0.x,av0.y,av0.z,av0.w, av1.x,av1.y,av1.z,av1.w};
            #pragma unroll
            for(int i=0;i<8;i++){
                ull aa = pack2(av[i], av[i]);
                #pragma unroll
                for(int j=0;j<4;j++) acc2[i][j] = ffma2(aa, bp[j], acc2[i][j]);
            }
        }
        __syncthreads();
    }
    #pragma unroll
    for(int i=0;i<8;i++){
        int row = (i<4) ? (ty*4+i) : (64 + ty*4 + (i-4));
        float c[8];
        unpack2(acc2[i][0], c[0], c[1]);
        unpack2(acc2[i][1], c[2], c[3]);
        unpack2(acc2[i][2], c[4], c[5]);
        unpack2(acc2[i][3], c[6], c[7]);
        if(mode==1){
            #pragma unroll
            for(int j=0;j<8;j++) c[j] *= sigmoidf(c[j]);
        }
        float4 c0; c0.x=c[0]; c0.y=c[1]; c0.z=c[2]; c0.w=c[3];
        float4 c1; c1.x=c[4]; c1.y=c[5]; c1.z=c[6]; c1.w=c[7];
        *(float4*)&Cb[(long long)row*ldc + tx*4] = c0;
        *(float4*)&Cb[(long long)row*ldc + 64 + tx*4] = c1;
    }
}

__global__ __launch_bounds__(256) void gemm128_gen(
    const float* __restrict__ A, long long sAz, int lda,
    const float* __restrict__ B, long long sBz, int ldb,
    float* __restrict__ C, long long sCz, int ldc,
    int K, int mode)
{
    const float* Ab = A + blockIdx.z*sAz + (long long)blockIdx.y*128*lda;
    const float* Bb = B + blockIdx.z*sBz + (long long)blockIdx.x*128*ldb;
    float* Cb = C + blockIdx.z*sCz + (long long)blockIdx.y*128*ldc + blockIdx.x*128;
    dev_gemm128(Ab, lda, Bb, ldb, Cb, ldc, K, mode);
}

__global__ __launch_bounds__(256) void gemm128_proj(
    const float* __restrict__ x, const float* __restrict__ wk,
    const float* __restrict__ wv, const float* __restrict__ wq)
{
    int w = blockIdx.z;
    const float* W = (w==0)?wk:((w==1)?wv:wq);
    float* dst = (w==0)?g_k:((w==1)?g_v:g_q);
    const float* Ab = x + (long long)blockIdx.y*128*Dc;
    const float* Bb = W + (long long)blockIdx.x*128*Dc;
    float* Cb = dst + (long long)blockIdx.y*128*Dc + blockIdx.x*128;
    dev_gemm128(Ab, Dc, Bb, Dc, Cb, Dc, Dc, 0);
}

// ---------------- gates ----------------
__global__ void gates_kernel(const float* __restrict__ x,
                             const float* __restrict__ thw,
                             const float* __restrict__ alw,
                             const float* __restrict__ etw){
    int row = blockIdx.x;
    const float* xr = x + (long long)row*Dc;
    float st=0.f, sa=0.f, se=0.f;
    for(int d=threadIdx.x; d<Dc; d+=128){
        float xv = xr[d];
        st += xv*thw[d]; sa += xv*alw[d]; se += xv*etw[d];
    }
    st = blockReduce(st); sa = blockReduce(sa); se = blockReduce(se);
    if(threadIdx.x == 0){
        g_theta[row] = 0.01f * sigmoidf(st);
        g_alpha[row] = sigmoidf(sa);
        g_eta[row]   = sigmoidf(se);
    }
}

// ---------------- fused activations for k, v, q ----------------
__global__ void act3_kernel(const float* __restrict__ kn, const float* __restrict__ qn){
    int which = blockIdx.x >> 11;
    int row = blockIdx.x & 2047;
    float* buf = (which==0) ? g_k : ((which==1) ? g_v : g_q);
    long long idx = (long long)row*Dc + threadIdx.x;
    float v = buf[idx];
    float sv = v*sigmoidf(v);
    if(which==1){ buf[idx] = sv; return; }
    const float* wnorm = (which==0) ? kn : qn;
    float s2 = blockReduce(sv*sv);
    float n = rsqrtf(s2*(1.f/Dc) + 1e-6f);
    buf[idx] = sv*n*wnorm[threadIdx.x];
}

// ==================== persistent chunk-loop kernel ====================
// 512 threads. Stages A(pa), B(pb), C(token), D(pd), E(rank+ln), 5 gridSyncs/chunk.
// A/B/D: 32x32 tile, K split between warpgroups (wg0: K[0:256), wg1: K[256:512)),
// each wg double-buffered over 8 k-tiles of 32; smem combine; wg0 epilogue.

// shared gemm slab: per wg 2 buffers x (A 1152 + B 1152)
__device__ __forceinline__ void wg_gemm_nt(
    const float* __restrict__ A, int lda,
    const float* __restrict__ B, int ldb,
    float* As, float* Bs, int lt, ull acc2[2])
{
    const int lm = lt>>3, lk = (lt&7)*4;
    const int r = lt>>3, cb = (lt&7)*4;
    float4 aN = *(const float4*)&A[(long long)lm*lda + lk];
    float4 bN = *(const float4*)&B[(long long)lm*ldb + lk];
    for(int kt=0;kt<8;kt++){
        float* Ac = As + (kt&1)*1152;
        float* Bc = Bs + (kt&1)*1152;
        Ac[(lk+0)*36+lm]=aN.x; Ac[(lk+1)*36+lm]=aN.y; Ac[(lk+2)*36+lm]=aN.z; Ac[(lk+3)*36+lm]=aN.w;
        Bc[(lk+0)*36+lm]=bN.x; Bc[(lk+1)*36+lm]=bN.y; Bc[(lk+2)*36+lm]=bN.z; Bc[(lk+3)*36+lm]=bN.w;
        __syncthreads();
        if(kt<7){
            int k0 = (kt+1)*32;
            aN = *(const float4*)&A[(long long)lm*lda + k0 + lk];
            bN = *(const float4*)&B[(long long)lm*ldb + k0 + lk];
        }
        #pragma unroll
        for(int kk=0;kk<32;kk++){
            float a = Ac[kk*36+r];
            ulonglong2 bq = *(ulonglong2*)&Bc[kk*36+cb];
            ull aa = pack2(a, a);
            acc2[0] = ffma2(aa, bq.x, acc2[0]);
            acc2[1] = ffma2(aa, bq.y, acc2[1]);
        }
    }
}

__device__ __forceinline__ void wg_gemm_nn(
    const float* __restrict__ A, int lda,
    const float* __restrict__ B, int ldb,   // B[k][n], 32-wide n tile at B
    float* As, float* Bs, int lt, ull acc2[2])
{
    const int lm = lt>>3, lk = (lt&7)*4;
    const int bk = lt>>3, bnb = (lt&7)*4;
    const int r = lt>>3, cb = (lt&7)*4;
    float4 aN = *(const float4*)&A[(long long)lm*lda + lk];
    float4 bN = *(const float4*)&B[(long long)bk*ldb + bnb];
    for(int kt=0;kt<8;kt++){
        float* Ac = As + (kt&1)*1152;
        float* Bc = Bs + (kt&1)*1152;
        Ac[(lk+0)*36+lm]=aN.x; Ac[(lk+1)*36+lm]=aN.y; Ac[(lk+2)*36+lm]=aN.z; Ac[(lk+3)*36+lm]=aN.w;
        *(float4*)&Bc[bk*36+bnb] = bN;
        __syncthreads();
        if(kt<7){
            int k0 = (kt+1)*32;
            aN = *(const float4*)&A[(long long)lm*lda + k0 + lk];
            bN = *(const float4*)&B[(long long)(k0+bk)*ldb + bnb];
        }
        #pragma unroll
        for(int kk=0;kk<32;kk++){
            float a = Ac[kk*36+r];
            ulonglong2 bq = *(ulonglong2*)&Bc[kk*36+cb];
            ull aa = pack2(a, a);
            acc2[0] = ffma2(aa, bq.x, acc2[0]);
            acc2[1] = ffma2(aa, bq.y, acc2[1]);
        }
    }
}

// combine the two wg partial accumulators; wg0 returns combined acc[4], others garbage
__device__ __forceinline__ bool wg_combine(float* SH, int tid, ull acc2[2], float acc[4]){
    int wg = tid>>8, lt = tid&255;
    __syncthreads();
    if(wg==1){
        float a0,a1,a2,a3;
        unpack2(acc2[0],a0,a1); unpack2(acc2[1],a2,a3);
        float4 v; v.x=a0; v.y=a1; v.z=a2; v.w=a3;
        *(float4*)&SH[lt*4] = v;
    }
    __syncthreads();
    if(wg==0){
        float a0,a1,a2,a3;
        unpack2(acc2[0],a0,a1); unpack2(acc2[1],a2,a3);
        float4 v = *(float4*)&SH[lt*4];
        acc[0]=a0+v.x; acc[1]=a1+v.y; acc[2]=a2+v.z; acc[3]=a3+v.w;
        return true;
    }
    return false;
}

__global__ void __launch_bounds__(512, 1) chunk_loop_kernel(int nb){
    __shared__ __align__(16) float SH[9472];
    const int bid = blockIdx.x, tid = threadIdx.x;
    const int wg = tid>>8, lt = tid&255;

    for(int ci=0; ci<NCc; ci++){
        // ---- Stage A: z/h = silu(Kc @ MW1^T) ----
        if(bid < 128){
            int b = bid>>5, nt = bid&31;
            const float* A = g_k + ((long long)b*Sc + ci*Cc)*Dc + wg*256;
            const float* B = g_MW1 + (long long)b*ID + (long long)nt*32*Dc + wg*256;
            ull acc2[2] = {0ull,0ull};
            wg_gemm_nt(A, Dc, B, Dc, SH + wg*4608, SH + wg*4608 + 2304, lt, acc2);
            float acc[4];
            if(wg_combine(SH, tid, acc2, acc)){
                int r = lt>>3, cb = (lt&7)*4;
                long long idx = (long long)b*CI + (long long)r*Ic + nt*32 + cb;
                float4 z4; z4.x=acc[0]; z4.y=acc[1]; z4.z=acc[2]; z4.w=acc[3];
                *(float4*)&g_z[idx] = z4;
                float4 h4;
                h4.x=acc[0]*sigmoidf(acc[0]); h4.y=acc[1]*sigmoidf(acc[1]);
                h4.z=acc[2]*sigmoidf(acc[2]); h4.w=acc[3]*sigmoidf(acc[3]);
                *(float4*)&g_h[idx] = h4;
            }
        }
        gridSync(nb);

        // ---- Stage B: o partials = H @ MW2^T (ks halves of Ic) ----
        if(bid < 128){
            int b = bid>>5, u = bid&31;
            int nt = u&15, ks = u>>4;
            const float* A = g_h + (long long)b*CI + ks*512 + wg*256;
            const float* B = g_MW2 + (long long)b*ID + (long long)nt*32*Ic + ks*512 + wg*256;
            ull acc2[2] = {0ull,0ull};
            wg_gemm_nt(A, Ic, B, Ic, SH + wg*4608, SH + wg*4608 + 2304, lt, acc2);
            float acc[4];
            if(wg_combine(SH, tid, acc2, acc)){
                int r = lt>>3, cb = (lt&7)*4;
                float* Cb = g_op + (long long)ks*(Bc*CD) + (long long)b*CD + nt*32;
                float4 o4; o4.x=acc[0]; o4.y=acc[1]; o4.z=acc[2]; o4.w=acc[3];
                *(float4*)&Cb[(long long)r*Dc + cb] = o4;
            }
        }
        gridSync(nb);

        // ---- Stage C: token backward + norms + scan recurrence ----
        if(bid < 128){
            int b = bid>>5, t = bid&31;
            int d = tid;
            int tok = ci*Cc + t;
            long long cidx = ((long long)b*Cc + t)*Dc + d;
            float kv = g_k[((long long)b*Sc + tok)*Dc + d];
            float vv = g_v[((long long)b*Sc + tok)*Dc + d];
            float ov = g_op[cidx] + g_op[(long long)Bc*CD + cidx];
            float ln = g_Mln[b*Dc + d];
            float th = g_theta[b*Sc + tok];
            float s2 = blockReduce(ov*ov);
            float n = rsqrtf(s2*(1.f/Dc) + 1e-6f);
            float y = ln*n*ov;
            float r = kv + y - vv;
            float u = (2.f/Dc)*th*r;
            float gl = u*n*ov;
            float ws = blockReduce(u*ov*ln);
            float dov = n*ln*u - (n*n*n*ov*(1.f/Dc))*ws;
            g_do[cidx] = dov;
            g_gln[cidx] = gl;
            float hv0 = g_h[((long long)b*Cc + t)*Ic + d];
            float hv1 = g_h[((long long)b*Cc + t)*Ic + d + 512];
            float nk = blockReduce(kv*kv);
            float nd = blockReduce(dov*dov);
            float ng = blockReduce(gl*gl);
            float nh = blockReduce(hv0*hv0 + hv1*hv1);
            if(d==0){
                g_nk[b*Cc+t]=nk; g_ndo[b*Cc+t]=nd; g_ngl[b*Cc+t]=ng; g_nh[b*Cc+t]=nh;
            }
            if(t==0){
                __shared__ float sEta[32], sBeta[32];
                if(d < 32){
                    sEta[d]  = g_eta[b*Sc + ci*Cc + d];
                    sBeta[d] = 1.f - g_alpha[b*Sc + ci*Cc + d];
                }
                __syncthreads();
                if(d==0){
                    float E=1.f, F=1.f, c=1.f, cSv=0.f;
                    for(int s=Cc-1;s>=0;s--){
                        g_sE[b*Cc+s] = E;
                        g_sc2[b*Cc+s] = c;
                        if(s==0) cSv = sEta[0]*c;
                        float Fn = sBeta[s]*F;
                        c = Fn + sEta[s]*c;
                        E = sEta[s]*E;
                        F = Fn;
                    }
                    g_Ab[b]=E; g_Bpb[b]=F; g_cSb[b]=cSv;
                }
                __syncthreads();
            }
        }
        gridSync(nb);

        // ---- Stage D: p = (DO @ MW2) * dsilu(z) + |p|^2 partials ----
        if(bid < 128){
            int b = bid>>5, nt = bid&31;
            const float* A = g_do + (long long)b*CD + wg*256;
            const float* B = g_MW2 + (long long)b*ID + (long long)(wg*256)*Ic + nt*32;
            ull acc2[2] = {0ull,0ull};
            wg_gemm_nn(A, Dc, B, Ic, SH + wg*4608, SH + wg*4608 + 2304, lt, acc2);
            float acc[4];
            if(wg_combine(SH, tid, acc2, acc)){
                int r = lt>>3, cb = (lt&7)*4;
                long long idx = (long long)b*CI + (long long)r*Ic + nt*32 + cb;
                float4 z4 = *(const float4*)&g_z[idx];
                float4 pv;
                { float s=sigmoidf(z4.x); pv.x=acc[0]*(s*(1.f+z4.x*(1.f-s))); }
                { float s=sigmoidf(z4.y); pv.y=acc[1]*(s*(1.f+z4.y*(1.f-s))); }
                { float s=sigmoidf(z4.z); pv.z=acc[2]*(s*(1.f+z4.z*(1.f-s))); }
                { float s=sigmoidf(z4.w); pv.w=acc[3]*(s*(1.f+z4.w*(1.f-s))); }
                *(float4*)&g_p[idx] = pv;
                float sp = pv.x*pv.x + pv.y*pv.y + pv.z*pv.z + pv.w*pv.w;
                sp += __shfl_xor_sync(0xffffffffu, sp, 1);
                sp += __shfl_xor_sync(0xffffffffu, sp, 2);
                sp += __shfl_xor_sync(0xffffffffu, sp, 4);
                if((lt&7)==0) g_npp[(b*Cc+r)*32 + nt] = sp;
            }
        }
        gridSync(nb);

        // ---- Stage E: rank-32 state updates (64x128 tiles, 512 thr) + ln ----
        for(int task = bid; task < 516; task += nb){
            __shared__ float sce[32], scc[32];
            float* Ps = SH;          // 32 x 68
            float* Ks = SH + 2176;   // 32 x 132
            int b;
            const float *P = nullptr, *Kv = nullptr;
            float *Sm = nullptr, *Mm = nullptr;
            int ld = 0, pStr = 0, kStr = 0;
            bool isLn = false;
            if(task < 256){
                int u = task; b = u>>6; int tile = u&63;
                int rt = tile>>2, ct = tile&3;
                Sm = g_SW1 + (long long)b*ID + (long long)rt*64*Dc + ct*128;
                Mm = g_MW1 + (long long)b*ID + (long long)rt*64*Dc + ct*128;
                ld = Dc;
                P  = g_p + (long long)b*CI + rt*64;   pStr = Ic;
                Kv = g_k + ((long long)b*Sc + ci*Cc)*Dc + ct*128;  kStr = Dc;
            } else if(task < 512){
                int u = task-256; b = u>>6; int tile = u&63;
                int rt = tile>>3, ct = tile&7;
                Sm = g_SW2 + (long long)b*ID + (long long)rt*64*Ic + ct*128;
                Mm = g_MW2 + (long long)b*ID + (long long)rt*64*Ic + ct*128;
                ld = Ic;
                P  = g_do + (long long)b*CD + rt*64;  pStr = Dc;
                Kv = g_h + (long long)b*CI + ct*128;  kStr = Ic;
            } else {
                isLn = true; b = task-512;
            }

            if(tid < 32){
                float np = 0.f;
                #pragma unroll
                for(int j=0;j<32;j++) np += g_npp[(b*Cc+tid)*32 + j];
                float sq = np*g_nk[b*Cc+tid] + g_ndo[b*Cc+tid]*g_nh[b*Cc+tid] + g_ngl[b*Cc+tid];
                float coef = fminf(1.f/(sqrtf(sq)+1e-6f), 1.f);
                sce[tid] = g_sE[b*Cc+tid]*coef;
                scc[tid] = g_sc2[b*Cc+tid]*coef;
            }

            if(isLn){
                __syncthreads();
                float A = g_Ab[b], Bp = g_Bpb[b], cS = g_cSb[b];
                int d = tid;
                float S = g_Sln[b*Dc+d], M = g_Mln[b*Dc+d];
                float se_=0.f, sc_=0.f;
                #pragma unroll
                for(int t2=0;t2<Cc;t2++){
                    float g = g_gln[((long long)b*Cc + t2)*Dc + d];
                    se_ += sce[t2]*g;
                    sc_ += scc[t2]*g;
                }
                g_Sln[b*Dc+d] = A*S - se_;
                g_Mln[b*Dc+d] = Bp*M + cS*S - sc_;
                __syncthreads();
                continue;
            }

            {   // load P (32x64) and K (32x128)
                int f = tid;
                int tt = f>>4, cbb = (f&15)*4;
                *(float4*)&Ps[tt*68+cbb] = *(const float4*)&P[(long long)tt*pStr + cbb];
                #pragma unroll
                for(int i=0;i<2;i++){
                    int f2 = tid*2 + i;
                    int tt2 = f2>>5, cb2 = (f2&31)*4;
                    *(float4*)&Ks[tt2*132+cb2] = *(const float4*)&Kv[(long long)tt2*kStr + cb2];
                }
            }
            __syncthreads();

            const int ty = tid>>4, tx = tid&15;   // rows ty*2..+1 (64), cols tx*8..+7 (128)
            ull ae2[2][4], ac2[2][4];
            #pragma unroll
            for(int i=0;i<2;i++){
                #pragma unroll
                for(int j=0;j<4;j++){ ae2[i][j]=0ull; ac2[i][j]=0ull; }
            }
            #pragma unroll
            for(int t=0;t<32;t++){
                float ce = sce[t], cc = scc[t];
                float2 p2 = *(float2*)&Ps[t*68 + ty*2];
                ulonglong2 kq0 = *(ulonglong2*)&Ks[t*132 + tx*8];
                ulonglong2 kq1 = *(ulonglong2*)&Ks[t*132 + tx*8 + 4];
                ull kp[4] = {kq0.x, kq0.y, kq1.x, kq1.y};
                float pvv[2] = {p2.x, p2.y};
                #pragma unroll
                for(int i=0;i<2;i++){
                    float pe = -ce*pvv[i], pc = -cc*pvv[i];
                    ull pe2 = pack2(pe, pe), pc2 = pack2(pc, pc);
                    #pragma unroll
                    for(int j=0;j<4;j++){
                        ae2[i][j] = ffma2(pe2, kp[j], ae2[i][j]);
                        ac2[i][j] = ffma2(pc2, kp[j], ac2[i][j]);
                    }
                }
            }
            float A = g_Ab[b], Bp = g_Bpb[b], cS = g_cSb[b];
            ull A2 = pack2(A,A), Bp2 = pack2(Bp,Bp), cS2 = pack2(cS,cS);
            #pragma unroll
            for(int i=0;i<2;i++){
                long long base = (long long)(ty*2+i)*ld + tx*8;
                #pragma unroll
                for(int half=0;half<2;half++){
                    ulonglong2 s2v = *(ulonglong2*)&Sm[base + half*4];
                    ulonglong2 m2v = *(ulonglong2*)&Mm[base + half*4];
                    int j0 = half*2;
                    ull ns0 = ffma2(A2, s2v.x, ae2[i][j0+0]);
                    ull ns1 = ffma2(A2, s2v.y, ae2[i][j0+1]);
                    ull t0  = ffma2(cS2, s2v.x, ac2[i][j0+0]);
                    ull t1  = ffma2(cS2, s2v.y, ac2[i][j0+1]);
                    ull nm0 = ffma2(Bp2, m2v.x, t0);
                    ull nm1 = ffma2(Bp2, m2v.y, t1);
                    ulonglong2 nsv; nsv.x=ns0; nsv.y=ns1;
                    ulonglong2 nmv; nmv.x=nm0; nmv.y=nm1;
                    *(ulonglong2*)&Sm[base + half*4] = nsv;
                    *(ulonglong2*)&Mm[base + half*4] = nmv;
                }
            }
            __syncthreads();
        }
        gridSync(nb);
    }
}

// ---------------- final combine ----------------
__global__ void final_kernel(float* __restrict__ out){
    int row = blockIdx.x, d = threadIdx.x;
    int b = row >> 9;
    long long idx = (long long)row*Dc + d;
    float qv = g_q[idx];
    float ov = g_obuf[idx];
    float ln = g_Mln[b*Dc + d];
    float s2 = blockReduce(ov*ov);
    float n = rsqrtf(s2*(1.f/Dc) + 1e-6f);
    out[idx] = qv + ov*n*ln;
}

extern "C" void kernel_launch(void* const* d_in, const int* in_sizes, int n_in,
                              void* d_out, int out_size){
    const float* x   = (const float*)d_in[0];
    const float* wq  = (const float*)d_in[1];
    const float* wk  = (const float*)d_in[2];
    const float* wv  = (const float*)d_in[3];
    const float* qn  = (const float*)d_in[4];
    const float* kn  = (const float*)d_in[5];
    const float* alw = (const float*)d_in[6];
    const float* thw = (const float*)d_in[7];
    const float* etw = (const float*)d_in[8];
    const float* w1  = (const float*)d_in[9];
    const float* w2  = (const float*)d_in[10];
    const float* lnw = (const float*)d_in[11];
    float* out = (float*)d_out;

    float *q_, *mw1_, *mw2_, *hbuf_, *obuf_;
    cudaGetSymbolAddress((void**)&q_, g_q);
    cudaGetSymbolAddress((void**)&mw1_, g_MW1);
    cudaGetSymbolAddress((void**)&mw2_, g_MW2);
    cudaGetSymbolAddress((void**)&hbuf_, g_hbuf);
    cudaGetSymbolAddress((void**)&obuf_, g_obuf);

    int nsm = 0;
    cudaDeviceGetAttribute(&nsm, cudaDevAttrMultiProcessorCount, 0);
    if(nsm <= 0) nsm = 148;
    if(nsm > 148) nsm = 148;   // 1 block/SM guaranteed resident

    init_kernel<<<ID/256, 256>>>(w1, w2, lnw);

    gemm128_proj<<<dim3(4, 16, 3), 256>>>(x, wk, wv, wq);
    gates_kernel<<<Bc*Sc, 128>>>(x, thw, alw, etw);
    act3_kernel<<<3*Bc*Sc, Dc>>>(kn, qn);

    chunk_loop_kernel<<<nsm, 512>>>(nsm);

    gemm128_gen<<<dim3(8, 4, 4), 256>>>(q_, SD, Dc, mw1_, ID, Dc, hbuf_, SI, Ic, 512, 1);
    gemm128_gen<<<dim3(4, 4, 4), 256>>>(hbuf_, SI, Ic, mw2_, ID, Ic, obuf_, SD, Dc, 1024, 0);
    final_kernel<<<Bc*Sc, Dc>>>(out);
}

// round 13
// speedup vs baseline: 1.0015x; 1.0015x over previous
#include <cuda_runtime.h>
#include <math.h>
#include <stdint.h>

constexpr int Bc=4, Sc=512, Dc=512, Ic=1024, Cc=32, NCc=16;
constexpr long long SD=(long long)Sc*Dc;
constexpr long long ID=(long long)Ic*Dc;
constexpr long long CI=(long long)Cc*Ic;
constexpr long long CD=(long long)Cc*Dc;
constexpr long long SI=(long long)Sc*Ic;

// ---------------- persistent device scratch ----------------
__device__ float g_k[Bc*Sc*Dc];
__device__ float g_v[Bc*Sc*Dc];
__device__ float g_q[Bc*Sc*Dc];
__device__ float g_theta[Bc*Sc];
__device__ float g_alpha[Bc*Sc];
__device__ float g_eta[Bc*Sc];
__device__ float g_MW1[Bc*Ic*Dc];
__device__ float g_SW1[Bc*Ic*Dc];
__device__ float g_MW2[Bc*Dc*Ic];
__device__ float g_SW2[Bc*Dc*Ic];
__device__ float g_Mln[Bc*Dc];
__device__ float g_Sln[Bc*Dc];
__device__ float g_z[Bc*Cc*Ic];
__device__ float g_h[Bc*Cc*Ic];
__device__ float g_op[2*Bc*Cc*Dc];
__device__ float g_do[Bc*Cc*Dc];
__device__ float g_gln[Bc*Cc*Dc];
__device__ float g_p[Bc*Cc*Ic];
__device__ float g_npp[Bc*Cc*32];
__device__ float g_nk[Bc*Cc], g_ndo[Bc*Cc], g_ngl[Bc*Cc], g_nh[Bc*Cc];
__device__ float g_sE[Bc*Cc], g_sc2[Bc*Cc];
__device__ float g_Ab[Bc], g_Bpb[Bc], g_cSb[Bc];
__device__ float g_hbuf[Bc*Sc*Ic];
__device__ float g_obuf[Bc*Sc*Dc];
__device__ int g_barCount;
__device__ int g_barGen;

__device__ __forceinline__ float sigmoidf(float v){ return 1.f/(1.f+expf(-v)); }

// ---------------- packed f32x2 primitives ----------------
typedef unsigned long long ull;

__device__ __forceinline__ ull pack2(float x, float y){
    ull r;
    asm("mov.b64 %0, {%1, %2};" : "=l"(r) : "r"(__float_as_uint(x)), "r"(__float_as_uint(y)));
    return r;
}
__device__ __forceinline__ void unpack2(ull v, float& x, float& y){
    unsigned int a, b;
    asm("mov.b64 {%0, %1}, %2;" : "=r"(a), "=r"(b) : "l"(v));
    x = __uint_as_float(a); y = __uint_as_float(b);
}
__device__ __forceinline__ ull ffma2(ull a, ull b, ull c){
    ull d;
    asm("fma.rn.f32x2 %0, %1, %2, %3;" : "=l"(d) : "l"(a), "l"(b), "l"(c));
    return d;
}

__device__ __forceinline__ float blockReduce(float v){
    __shared__ float sred[33];
    int lane = threadIdx.x & 31, w = threadIdx.x >> 5;
    #pragma unroll
    for(int o=16;o>0;o>>=1) v += __shfl_down_sync(0xffffffffu, v, o);
    if(lane==0) sred[w] = v;
    __syncthreads();
    int nw = (blockDim.x + 31) >> 5;
    if(w==0){
        float r = (lane < nw) ? sred[lane] : 0.f;
        #pragma unroll
        for(int o=16;o>0;o>>=1) r += __shfl_down_sync(0xffffffffu, r, o);
        if(lane==0) sred[32] = r;
    }
    __syncthreads();
    float r = sred[32];
    __syncthreads();
    return r;
}

// ---------------- grid barrier (all blocks resident: grid = #SMs, 1 block/SM) ----------------
__device__ __forceinline__ void gridSync(int nb){
    __syncthreads();
    if(threadIdx.x==0){
        int gen = *((volatile int*)&g_barGen);
        __threadfence();
        if(atomicAdd(&g_barCount, 1) == nb-1){
            g_barCount = 0;
            __threadfence();
            atomicExch(&g_barGen, gen+1);
        } else {
            while(*((volatile int*)&g_barGen) == gen){ __nanosleep(40); }
            __threadfence();
        }
    }
    __syncthreads();
}

// ---------------- init ----------------
__global__ void init_kernel(const float* __restrict__ w1, const float* __restrict__ w2,
                            const float* __restrict__ lnw){
    int idx = blockIdx.x*256 + threadIdx.x;
    float a = w1[idx], b2 = w2[idx];
    #pragma unroll
    for(int b=0;b<Bc;b++){
        g_MW1[b*Ic*Dc + idx] = a;   g_SW1[b*Ic*Dc + idx] = 0.f;
        g_MW2[b*Dc*Ic + idx] = b2;  g_SW2[b*Dc*Ic + idx] = 0.f;
    }
    if(idx < Dc){
        float l = lnw[idx];
        #pragma unroll
        for(int b=0;b<Bc;b++){ g_Mln[b*Dc+idx] = l; g_Sln[b*Dc+idx] = 0.f; }
    }
}

// ---------------- 128x128 NT tile, 256 threads, FFMA2 (projections + retrieval) ----------------
__device__ __forceinline__ void dev_gemm128(
    const float* __restrict__ Ab, int lda,
    const float* __restrict__ Bb, int ldb,
    float* __restrict__ Cb, int ldc,
    int K, int mode)
{
    __shared__ float As[16*132];
    __shared__ float Bs[16*132];
    const int tid = threadIdx.x;
    const int ty = tid>>4, tx = tid&15;
    ull acc2[8][4];
    #pragma unroll
    for(int i=0;i<8;i++){
        #pragma unroll
        for(int j=0;j<4;j++) acc2[i][j] = 0ull;
    }
    const int lf = tid*2;
    const int m0 = lf>>2,     ka0 = (lf&3)*4;
    const int m1 = (lf+1)>>2, ka1 = ((lf+1)&3)*4;
    for(int k0=0;k0<K;k0+=16){
        float4 a0 = *(const float4*)&Ab[(long long)m0*lda + k0 + ka0];
        float4 a1 = *(const float4*)&Ab[(long long)m1*lda + k0 + ka1];
        float4 b0 = *(const float4*)&Bb[(long long)m0*ldb + k0 + ka0];
        float4 b1 = *(const float4*)&Bb[(long long)m1*ldb + k0 + ka1];
        As[(ka0+0)*132+m0]=a0.x; As[(ka0+1)*132+m0]=a0.y; As[(ka0+2)*132+m0]=a0.z; As[(ka0+3)*132+m0]=a0.w;
        As[(ka1+0)*132+m1]=a1.x; As[(ka1+1)*132+m1]=a1.y; As[(ka1+2)*132+m1]=a1.z; As[(ka1+3)*132+m1]=a1.w;
        Bs[(ka0+0)*132+m0]=b0.x; Bs[(ka0+1)*132+m0]=b0.y; Bs[(ka0+2)*132+m0]=b0.z; Bs[(ka0+3)*132+m0]=b0.w;
        Bs[(ka1+0)*132+m1]=b1.x; Bs[(ka1+1)*132+m1]=b1.y; Bs[(ka1+2)*132+m1]=b1.z; Bs[(ka1+3)*132+m1]=b1.w;
        __syncthreads();
        #pragma unroll
        for(int kk=0;kk<16;kk++){
            float4 av0 = *(float4*)&As[kk*132 + ty*4];
            float4 av1 = *(float4*)&As[kk*132 + 64 + ty*4];
            ulonglong2 bq0 = *(ulonglong2*)&Bs[kk*132 + tx*4];
            ulonglong2 bq1 = *(ulonglong2*)&Bs[kk*132 + 64 + tx*4];
            ull bp[4] = {bq0.x, bq0.y, bq1.x, bq1.y};
            float av[8] = {av0.x,av0.y,av0.z,av0.w, av1.x,av1.y,av1.z,av1.w};
            #pragma unroll
            for(int i=0;i<8;i++){
                ull aa = pack2(av[i], av[i]);
                #pragma unroll
                for(int j=0;j<4;j++) acc2[i][j] = ffma2(aa, bp[j], acc2[i][j]);
            }
        }
        __syncthreads();
    }
    #pragma unroll
    for(int i=0;i<8;i++){
        int row = (i<4) ? (ty*4+i) : (64 + ty*4 + (i-4));
        float c[8];
        unpack2(acc2[i][0], c[0], c[1]);
        unpack2(acc2[i][1], c[2], c[3]);
        unpack2(acc2[i][2], c[4], c[5]);
        unpack2(acc2[i][3], c[6], c[7]);
        if(mode==1){
            #pragma unroll
            for(int j=0;j<8;j++) c[j] *= sigmoidf(c[j]);
        }
        float4 c0; c0.x=c[0]; c0.y=c[1]; c0.z=c[2]; c0.w=c[3];
        float4 c1; c1.x=c[4]; c1.y=c[5]; c1.z=c[6]; c1.w=c[7];
        *(float4*)&Cb[(long long)row*ldc + tx*4] = c0;
        *(float4*)&Cb[(long long)row*ldc + 64 + tx*4] = c1;
    }
}

__global__ __launch_bounds__(256) void gemm128_gen(
    const float* __restrict__ A, long long sAz, int lda,
    const float* __restrict__ B, long long sBz, int ldb,
    float* __restrict__ C, long long sCz, int ldc,
    int K, int mode)
{
    const float* Ab = A + blockIdx.z*sAz + (long long)blockIdx.y*128*lda;
    const float* Bb = B + blockIdx.z*sBz + (long long)blockIdx.x*128*ldb;
    float* Cb = C + blockIdx.z*sCz + (long long)blockIdx.y*128*ldc + blockIdx.x*128;
    dev_gemm128(Ab, lda, Bb, ldb, Cb, ldc, K, mode);
}

__global__ __launch_bounds__(256) void gemm128_proj(
    const float* __restrict__ x, const float* __restrict__ wk,
    const float* __restrict__ wv, const float* __restrict__ wq)
{
    int w = blockIdx.z;
    const float* W = (w==0)?wk:((w==1)?wv:wq);
    float* dst = (w==0)?g_k:((w==1)?g_v:g_q);
    const float* Ab = x + (long long)blockIdx.y*128*Dc;
    const float* Bb = W + (long long)blockIdx.x*128*Dc;
    float* Cb = dst + (long long)blockIdx.y*128*Dc + blockIdx.x*128;
    dev_gemm128(Ab, Dc, Bb, Dc, Cb, Dc, Dc, 0);
}

// ---------------- gates ----------------
__global__ void gates_kernel(const float* __restrict__ x,
                             const float* __restrict__ thw,
                             const float* __restrict__ alw,
                             const float* __restrict__ etw){
    int row = blockIdx.x;
    const float* xr = x + (long long)row*Dc;
    float st=0.f, sa=0.f, se=0.f;
    for(int d=threadIdx.x; d<Dc; d+=128){
        float xv = xr[d];
        st += xv*thw[d]; sa += xv*alw[d]; se += xv*etw[d];
    }
    st = blockReduce(st); sa = blockReduce(sa); se = blockReduce(se);
    if(threadIdx.x == 0){
        g_theta[row] = 0.01f * sigmoidf(st);
        g_alpha[row] = sigmoidf(sa);
        g_eta[row]   = sigmoidf(se);
    }
}

// ---------------- fused activations for k, v, q ----------------
__global__ void act3_kernel(const float* __restrict__ kn, const float* __restrict__ qn){
    int which = blockIdx.x >> 11;
    int row = blockIdx.x & 2047;
    float* buf = (which==0) ? g_k : ((which==1) ? g_v : g_q);
    long long idx = (long long)row*Dc + threadIdx.x;
    float v = buf[idx];
    float sv = v*sigmoidf(v);
    if(which==1){ buf[idx] = sv; return; }
    const float* wnorm = (which==0) ? kn : qn;
    float s2 = blockReduce(sv*sv);
    float n = rsqrtf(s2*(1.f/Dc) + 1e-6f);
    buf[idx] = sv*n*wnorm[threadIdx.x];
}

// ==================== persistent chunk-loop kernel ====================
// 512 threads. Stages A(pa), B(pb), C(token), D(pd), E(rank+ln), 5 gridSyncs/chunk.
// A/B/D: 32x32 tile, K split between warpgroups (wg0: K[0:256), wg1: K[256:512)),
// each wg double-buffered over 8 k-tiles of 32; smem combine; wg0 epilogue.

// shared gemm slab: per wg 2 buffers x (A 1152 + B 1152)
__device__ __forceinline__ void wg_gemm_nt(
    const float* __restrict__ A, int lda,
    const float* __restrict__ B, int ldb,
    float* As, float* Bs, int lt, ull acc2[2])
{
    const int lm = lt>>3, lk = (lt&7)*4;
    const int r = lt>>3, cb = (lt&7)*4;
    float4 aN = *(const float4*)&A[(long long)lm*lda + lk];
    float4 bN = *(const float4*)&B[(long long)lm*ldb + lk];
    for(int kt=0;kt<8;kt++){
        float* Ac = As + (kt&1)*1152;
        float* Bc = Bs + (kt&1)*1152;
        Ac[(lk+0)*36+lm]=aN.x; Ac[(lk+1)*36+lm]=aN.y; Ac[(lk+2)*36+lm]=aN.z; Ac[(lk+3)*36+lm]=aN.w;
        Bc[(lk+0)*36+lm]=bN.x; Bc[(lk+1)*36+lm]=bN.y; Bc[(lk+2)*36+lm]=bN.z; Bc[(lk+3)*36+lm]=bN.w;
        __syncthreads();
        if(kt<7){
            int k0 = (kt+1)*32;
            aN = *(const float4*)&A[(long long)lm*lda + k0 + lk];
            bN = *(const float4*)&B[(long long)lm*ldb + k0 + lk];
        }
        #pragma unroll
        for(int kk=0;kk<32;kk++){
            float a = Ac[kk*36+r];
            ulonglong2 bq = *(ulonglong2*)&Bc[kk*36+cb];
            ull aa = pack2(a, a);
            acc2[0] = ffma2(aa, bq.x, acc2[0]);
            acc2[1] = ffma2(aa, bq.y, acc2[1]);
        }
    }
}

__device__ __forceinline__ void wg_gemm_nn(
    const float* __restrict__ A, int lda,
    const float* __restrict__ B, int ldb,   // B[k][n], 32-wide n tile at B
    float* As, float* Bs, int lt, ull acc2[2])
{
    const int lm = lt>>3, lk = (lt&7)*4;
    const int bk = lt>>3, bnb = (lt&7)*4;
    const int r = lt>>3, cb = (lt&7)*4;
    float4 aN = *(const float4*)&A[(long long)lm*lda + lk];
    float4 bN = *(const float4*)&B[(long long)bk*ldb + bnb];
    for(int kt=0;kt<8;kt++){
        float* Ac = As + (kt&1)*1152;
        float* Bc = Bs + (kt&1)*1152;
        Ac[(lk+0)*36+lm]=aN.x; Ac[(lk+1)*36+lm]=aN.y; Ac[(lk+2)*36+lm]=aN.z; Ac[(lk+3)*36+lm]=aN.w;
        *(float4*)&Bc[bk*36+bnb] = bN;
        __syncthreads();
        if(kt<7){
            int k0 = (kt+1)*32;
            aN = *(const float4*)&A[(long long)lm*lda + k0 + lk];
            bN = *(const float4*)&B[(long long)(k0+bk)*ldb + bnb];
        }
        #pragma unroll
        for(int kk=0;kk<32;kk++){
            float a = Ac[kk*36+r];
            ulonglong2 bq = *(ulonglong2*)&Bc[kk*36+cb];
            ull aa = pack2(a, a);
            acc2[0] = ffma2(aa, bq.x, acc2[0]);
            acc2[1] = ffma2(aa, bq.y, acc2[1]);
        }
    }
}

// combine the two wg partial accumulators; wg0 returns combined acc[4], others garbage
__device__ __forceinline__ bool wg_combine(float* SH, int tid, ull acc2[2], float acc[4]){
    int wg = tid>>8, lt = tid&255;
    __syncthreads();
    if(wg==1){
        float a0,a1,a2,a3;
        unpack2(acc2[0],a0,a1); unpack2(acc2[1],a2,a3);
        float4 v; v.x=a0; v.y=a1; v.z=a2; v.w=a3;
        *(float4*)&SH[lt*4] = v;
    }
    __syncthreads();
    if(wg==0){
        float a0,a1,a2,a3;
        unpack2(acc2[0],a0,a1); unpack2(acc2[1],a2,a3);
        float4 v = *(float4*)&SH[lt*4];
        acc[0]=a0+v.x; acc[1]=a1+v.y; acc[2]=a2+v.z; acc[3]=a3+v.w;
        return true;
    }
    return false;
}

__global__ void __launch_bounds__(512, 1) chunk_loop_kernel(int nb){
    __shared__ __align__(16) float SH[9472];
    const int bid = blockIdx.x, tid = threadIdx.x;
    const int wg = tid>>8, lt = tid&255;

    for(int ci=0; ci<NCc; ci++){
        // ---- Stage A: z/h = silu(Kc @ MW1^T) ----
        if(bid < 128){
            int b = bid>>5, nt = bid&31;
            const float* A = g_k + ((long long)b*Sc + ci*Cc)*Dc + wg*256;
            const float* B = g_MW1 + (long long)b*ID + (long long)nt*32*Dc + wg*256;
            ull acc2[2] = {0ull,0ull};
            wg_gemm_nt(A, Dc, B, Dc, SH + wg*4608, SH + wg*4608 + 2304, lt, acc2);
            float acc[4];
            if(wg_combine(SH, tid, acc2, acc)){
                int r = lt>>3, cb = (lt&7)*4;
                long long idx = (long long)b*CI + (long long)r*Ic + nt*32 + cb;
                float4 z4; z4.x=acc[0]; z4.y=acc[1]; z4.z=acc[2]; z4.w=acc[3];
                *(float4*)&g_z[idx] = z4;
                float4 h4;
                h4.x=acc[0]*sigmoidf(acc[0]); h4.y=acc[1]*sigmoidf(acc[1]);
                h4.z=acc[2]*sigmoidf(acc[2]); h4.w=acc[3]*sigmoidf(acc[3]);
                *(float4*)&g_h[idx] = h4;
            }
        }
        gridSync(nb);

        // ---- Stage B: o partials = H @ MW2^T (ks halves of Ic) ----
        if(bid < 128){
            int b = bid>>5, u = bid&31;
            int nt = u&15, ks = u>>4;
            const float* A = g_h + (long long)b*CI + ks*512 + wg*256;
            const float* B = g_MW2 + (long long)b*ID + (long long)nt*32*Ic + ks*512 + wg*256;
            ull acc2[2] = {0ull,0ull};
            wg_gemm_nt(A, Ic, B, Ic, SH + wg*4608, SH + wg*4608 + 2304, lt, acc2);
            float acc[4];
            if(wg_combine(SH, tid, acc2, acc)){
                int r = lt>>3, cb = (lt&7)*4;
                float* Cb = g_op + (long long)ks*(Bc*CD) + (long long)b*CD + nt*32;
                float4 o4; o4.x=acc[0]; o4.y=acc[1]; o4.z=acc[2]; o4.w=acc[3];
                *(float4*)&Cb[(long long)r*Dc + cb] = o4;
            }
        }
        gridSync(nb);

        // ---- Stage C: token backward + norms + scan recurrence ----
        if(bid < 128){
            int b = bid>>5, t = bid&31;
            int d = tid;
            int tok = ci*Cc + t;
            long long cidx = ((long long)b*Cc + t)*Dc + d;
            float kv = g_k[((long long)b*Sc + tok)*Dc + d];
            float vv = g_v[((long long)b*Sc + tok)*Dc + d];
            float ov = g_op[cidx] + g_op[(long long)Bc*CD + cidx];
            float ln = g_Mln[b*Dc + d];
            float th = g_theta[b*Sc + tok];
            float s2 = blockReduce(ov*ov);
            float n = rsqrtf(s2*(1.f/Dc) + 1e-6f);
            float y = ln*n*ov;
            float r = kv + y - vv;
            float u = (2.f/Dc)*th*r;
            float gl = u*n*ov;
            float ws = blockReduce(u*ov*ln);
            float dov = n*ln*u - (n*n*n*ov*(1.f/Dc))*ws;
            g_do[cidx] = dov;
            g_gln[cidx] = gl;
            float hv0 = g_h[((long long)b*Cc + t)*Ic + d];
            float hv1 = g_h[((long long)b*Cc + t)*Ic + d + 512];
            float nk = blockReduce(kv*kv);
            float nd = blockReduce(dov*dov);
            float ng = blockReduce(gl*gl);
            float nh = blockReduce(hv0*hv0 + hv1*hv1);
            if(d==0){
                g_nk[b*Cc+t]=nk; g_ndo[b*Cc+t]=nd; g_ngl[b*Cc+t]=ng; g_nh[b*Cc+t]=nh;
            }
            if(t==0){
                __shared__ float sEta[32], sBeta[32];
                if(d < 32){
                    sEta[d]  = g_eta[b*Sc + ci*Cc + d];
                    sBeta[d] = 1.f - g_alpha[b*Sc + ci*Cc + d];
                }
                __syncthreads();
                if(d==0){
                    float E=1.f, F=1.f, c=1.f, cSv=0.f;
                    for(int s=Cc-1;s>=0;s--){
                        g_sE[b*Cc+s] = E;
                        g_sc2[b*Cc+s] = c;
                        if(s==0) cSv = sEta[0]*c;
                        float Fn = sBeta[s]*F;
                        c = Fn + sEta[s]*c;
                        E = sEta[s]*E;
                        F = Fn;
                    }
                    g_Ab[b]=E; g_Bpb[b]=F; g_cSb[b]=cSv;
                }
                __syncthreads();
            }
        }
        gridSync(nb);

        // ---- Stage D: p = (DO @ MW2) * dsilu(z) + |p|^2 partials ----
        if(bid < 128){
            int b = bid>>5, nt = bid&31;
            const float* A = g_do + (long long)b*CD + wg*256;
            const float* B = g_MW2 + (long long)b*ID + (long long)(wg*256)*Ic + nt*32;
            ull acc2[2] = {0ull,0ull};
            wg_gemm_nn(A, Dc, B, Ic, SH + wg*4608, SH + wg*4608 + 2304, lt, acc2);
            float acc[4];
            if(wg_combine(SH, tid, acc2, acc)){
                int r = lt>>3, cb = (lt&7)*4;
                long long idx = (long long)b*CI + (long long)r*Ic + nt*32 + cb;
                float4 z4 = *(const float4*)&g_z[idx];
                float4 pv;
                { float s=sigmoidf(z4.x); pv.x=acc[0]*(s*(1.f+z4.x*(1.f-s))); }
                { float s=sigmoidf(z4.y); pv.y=acc[1]*(s*(1.f+z4.y*(1.f-s))); }
                { float s=sigmoidf(z4.z); pv.z=acc[2]*(s*(1.f+z4.z*(1.f-s))); }
                { float s=sigmoidf(z4.w); pv.w=acc[3]*(s*(1.f+z4.w*(1.f-s))); }
                *(float4*)&g_p[idx] = pv;
                float sp = pv.x*pv.x + pv.y*pv.y + pv.z*pv.z + pv.w*pv.w;
                sp += __shfl_xor_sync(0xffffffffu, sp, 1);
                sp += __shfl_xor_sync(0xffffffffu, sp, 2);
                sp += __shfl_xor_sync(0xffffffffu, sp, 4);
                if((lt&7)==0) g_npp[(b*Cc+r)*32 + nt] = sp;
            }
        }
        gridSync(nb);

        // ---- Stage E: rank-32 state updates (64x128 tiles, 512 thr) + ln ----
        for(int task = bid; task < 516; task += nb){
            __shared__ float sce[32], scc[32];
            float* Ps = SH;          // 32 x 68
            float* Ks = SH + 2176;   // 32 x 132
            int b;
            const float *P = nullptr, *Kv = nullptr;
            float *Sm = nullptr, *Mm = nullptr;
            int ld = 0, pStr = 0, kStr = 0;
            bool isLn = false;
            if(task < 256){
                int u = task; b = u>>6; int tile = u&63;
                int rt = tile>>2, ct = tile&3;
                Sm = g_SW1 + (long long)b*ID + (long long)rt*64*Dc + ct*128;
                Mm = g_MW1 + (long long)b*ID + (long long)rt*64*Dc + ct*128;
                ld = Dc;
                P  = g_p + (long long)b*CI + rt*64;   pStr = Ic;
                Kv = g_k + ((long long)b*Sc + ci*Cc)*Dc + ct*128;  kStr = Dc;
            } else if(task < 512){
                int u = task-256; b = u>>6; int tile = u&63;
                int rt = tile>>3, ct = tile&7;
                Sm = g_SW2 + (long long)b*ID + (long long)rt*64*Ic + ct*128;
                Mm = g_MW2 + (long long)b*ID + (long long)rt*64*Ic + ct*128;
                ld = Ic;
                P  = g_do + (long long)b*CD + rt*64;  pStr = Dc;
                Kv = g_h + (long long)b*CI + ct*128;  kStr = Ic;
            } else {
                isLn = true; b = task-512;
            }

            if(tid < 32){
                float np = 0.f;
                #pragma unroll
                for(int j=0;j<32;j++) np += g_npp[(b*Cc+tid)*32 + j];
                float sq = np*g_nk[b*Cc+tid] + g_ndo[b*Cc+tid]*g_nh[b*Cc+tid] + g_ngl[b*Cc+tid];
                float coef = fminf(1.f/(sqrtf(sq)+1e-6f), 1.f);
                sce[tid] = g_sE[b*Cc+tid]*coef;
                scc[tid] = g_sc2[b*Cc+tid]*coef;
            }

            if(isLn){
                __syncthreads();
                float A = g_Ab[b], Bp = g_Bpb[b], cS = g_cSb[b];
                int d = tid;
                float S = g_Sln[b*Dc+d], M = g_Mln[b*Dc+d];
                float se_=0.f, sc_=0.f;
                #pragma unroll
                for(int t2=0;t2<Cc;t2++){
                    float g = g_gln[((long long)b*Cc + t2)*Dc + d];
                    se_ += sce[t2]*g;
                    sc_ += scc[t2]*g;
                }
                g_Sln[b*Dc+d] = A*S - se_;
                g_Mln[b*Dc+d] = Bp*M + cS*S - sc_;
                __syncthreads();
                continue;
            }

            {   // load P (32x64) and K (32x128)
                int f = tid;
                int tt = f>>4, cbb = (f&15)*4;
                *(float4*)&Ps[tt*68+cbb] = *(const float4*)&P[(long long)tt*pStr + cbb];
                #pragma unroll
                for(int i=0;i<2;i++){
                    int f2 = tid*2 + i;
                    int tt2 = f2>>5, cb2 = (f2&31)*4;
                    *(float4*)&Ks[tt2*132+cb2] = *(const float4*)&Kv[(long long)tt2*kStr + cb2];
                }
            }
            __syncthreads();

            const int ty = tid>>4, tx = tid&15;   // rows ty*2..+1 (64), cols tx*8..+7 (128)
            ull ae2[2][4], ac2[2][4];
            #pragma unroll
            for(int i=0;i<2;i++){
                #pragma unroll
                for(int j=0;j<4;j++){ ae2[i][j]=0ull; ac2[i][j]=0ull; }
            }
            #pragma unroll
            for(int t=0;t<32;t++){
                float ce = sce[t], cc = scc[t];
                float2 p2 = *(float2*)&Ps[t*68 + ty*2];
                ulonglong2 kq0 = *(ulonglong2*)&Ks[t*132 + tx*8];
                ulonglong2 kq1 = *(ulonglong2*)&Ks[t*132 + tx*8 + 4];
                ull kp[4] = {kq0.x, kq0.y, kq1.x, kq1.y};
                float pvv[2] = {p2.x, p2.y};
                #pragma unroll
                for(int i=0;i<2;i++){
                    float pe = -ce*pvv[i], pc = -cc*pvv[i];
                    ull pe2 = pack2(pe, pe), pc2 = pack2(pc, pc);
                    #pragma unroll
                    for(int j=0;j<4;j++){
                        ae2[i][j] = ffma2(pe2, kp[j], ae2[i][j]);
                        ac2[i][j] = ffma2(pc2, kp[j], ac2[i][j]);
                    }
                }
            }
            float A = g_Ab[b], Bp = g_Bpb[b], cS = g_cSb[b];
            ull A2 = pack2(A,A), Bp2 = pack2(Bp,Bp), cS2 = pack2(cS,cS);
            #pragma unroll
            for(int i=0;i<2;i++){
                long long base = (long long)(ty*2+i)*ld + tx*8;
                #pragma unroll
                for(int half=0;half<2;half++){
                    ulonglong2 s2v = *(ulonglong2*)&Sm[base + half*4];
                    ulonglong2 m2v = *(ulonglong2*)&Mm[base + half*4];
                    int j0 = half*2;
                    ull ns0 = ffma2(A2, s2v.x, ae2[i][j0+0]);
                    ull ns1 = ffma2(A2, s2v.y, ae2[i][j0+1]);
                    ull t0  = ffma2(cS2, s2v.x, ac2[i][j0+0]);
                    ull t1  = ffma2(cS2, s2v.y, ac2[i][j0+1]);
                    ull nm0 = ffma2(Bp2, m2v.x, t0);
                    ull nm1 = ffma2(Bp2, m2v.y, t1);
                    ulonglong2 nsv; nsv.x=ns0; nsv.y=ns1;
                    ulonglong2 nmv; nmv.x=nm0; nmv.y=nm1;
                    *(ulonglong2*)&Sm[base + half*4] = nsv;
                    *(ulonglong2*)&Mm[base + half*4] = nmv;
                }
            }
            __syncthreads();
        }
        gridSync(nb);
    }
}

// ---------------- final combine ----------------
__global__ void final_kernel(float* __restrict__ out){
    int row = blockIdx.x, d = threadIdx.x;
    int b = row >> 9;
    long long idx = (long long)row*Dc + d;
    float qv = g_q[idx];
    float ov = g_obuf[idx];
    float ln = g_Mln[b*Dc + d];
    float s2 = blockReduce(ov*ov);
    float n = rsqrtf(s2*(1.f/Dc) + 1e-6f);
    out[idx] = qv + ov*n*ln;
}

extern "C" void kernel_launch(void* const* d_in, const int* in_sizes, int n_in,
                              void* d_out, int out_size){
    const float* x   = (const float*)d_in[0];
    const float* wq  = (const float*)d_in[1];
    const float* wk  = (const float*)d_in[2];
    const float* wv  = (const float*)d_in[3];
    const float* qn  = (const float*)d_in[4];
    const float* kn  = (const float*)d_in[5];
    const float* alw = (const float*)d_in[6];
    const float* thw = (const float*)d_in[7];
    const float* etw = (const float*)d_in[8];
    const float* w1  = (const float*)d_in[9];
    const float* w2  = (const float*)d_in[10];
    const float* lnw = (const float*)d_in[11];
    float* out = (float*)d_out;

    float *q_, *mw1_, *mw2_, *hbuf_, *obuf_;
    cudaGetSymbolAddress((void**)&q_, g_q);
    cudaGetSymbolAddress((void**)&mw1_, g_MW1);
    cudaGetSymbolAddress((void**)&mw2_, g_MW2);
    cudaGetSymbolAddress((void**)&hbuf_, g_hbuf);
    cudaGetSymbolAddress((void**)&obuf_, g_obuf);

    int nsm = 0;
    cudaDeviceGetAttribute(&nsm, cudaDevAttrMultiProcessorCount, 0);
    if(nsm <= 0) nsm = 148;
    if(nsm > 148) nsm = 148;   // 1 block/SM guaranteed resident

    init_kernel<<<ID/256, 256>>>(w1, w2, lnw);

    gemm128_proj<<<dim3(4, 16, 3), 256>>>(x, wk, wv, wq);
    gates_kernel<<<Bc*Sc, 128>>>(x, thw, alw, etw);
    act3_kernel<<<3*Bc*Sc, Dc>>>(kn, qn);

    chunk_loop_kernel<<<nsm, 512>>>(nsm);

    gemm128_gen<<<dim3(8, 4, 4), 256>>>(q_, SD, Dc, mw1_, ID, Dc, hbuf_, SI, Ic, 512, 1);
    gemm128_gen<<<dim3(4, 4, 4), 256>>>(hbuf_, SI, Ic, mw2_, ID, Ic, obuf_, SD, Dc, 1024, 0);
    final_kernel<<<Bc*Sc, Dc>>>(out);
}

// round 16
// speedup vs baseline: 1.0928x; 1.0911x over previous
#include <cuda_runtime.h>
#include <math.h>
#include <stdint.h>

constexpr int Bc=4, Sc=512, Dc=512, Ic=1024, Cc=32, NCc=16;
constexpr long long SD=(long long)Sc*Dc;
constexpr long long ID=(long long)Ic*Dc;
constexpr long long CI=(long long)Cc*Ic;
constexpr long long CD=(long long)Cc*Dc;
constexpr long long SI=(long long)Sc*Ic;

// ---------------- persistent device scratch ----------------
__device__ float g_k[Bc*Sc*Dc];
__device__ float g_v[Bc*Sc*Dc];
__device__ float g_q[Bc*Sc*Dc];
__device__ float g_theta[Bc*Sc];
__device__ float g_alpha[Bc*Sc];
__device__ float g_eta[Bc*Sc];
__device__ float g_MW1[Bc*Ic*Dc];
__device__ float g_SW1[Bc*Ic*Dc];
__device__ float g_MW2[Bc*Dc*Ic];
__device__ float g_SW2[Bc*Dc*Ic];
__device__ float g_Mln[Bc*Dc];
__device__ float g_Sln[Bc*Dc];
__device__ float g_z[Bc*Cc*Ic];
__device__ float g_h[Bc*Cc*Ic];
__device__ float g_op[2*Bc*Cc*Dc];
__device__ float g_do[Bc*Cc*Dc];
__device__ float g_gln[Bc*Cc*Dc];
__device__ float g_p[Bc*Cc*Ic];
__device__ float g_npp[Bc*Cc*32];
__device__ float g_nk[Bc*Cc], g_ndo[Bc*Cc], g_ngl[Bc*Cc], g_nh[Bc*Cc];
__device__ float g_sE[Bc*Cc], g_sc2[Bc*Cc];
__device__ float g_Ab[Bc], g_Bpb[Bc], g_cSb[Bc];
__device__ float g_hbuf[Bc*Sc*Ic];
__device__ float g_obuf[Bc*Sc*Dc];

__device__ __forceinline__ float sigmoidf(float v){ return 1.f/(1.f+expf(-v)); }

__device__ __forceinline__ float blockReduce(float v){
    __shared__ float sred[33];
    int lane = threadIdx.x & 31, w = threadIdx.x >> 5;
    #pragma unroll
    for(int o=16;o>0;o>>=1) v += __shfl_down_sync(0xffffffffu, v, o);
    if(lane==0) sred[w] = v;
    __syncthreads();
    int nw = (blockDim.x + 31) >> 5;
    if(w==0){
        float r = (lane < nw) ? sred[lane] : 0.f;
        #pragma unroll
        for(int o=16;o>0;o>>=1) r += __shfl_down_sync(0xffffffffu, r, o);
        if(lane==0) sred[32] = r;
    }
    __syncthreads();
    float r = sred[32];
    __syncthreads();
    return r;
}

// ---------------- init ----------------
__global__ void init_kernel(const float* __restrict__ w1, const float* __restrict__ w2,
                            const float* __restrict__ lnw){
    int idx = blockIdx.x*256 + threadIdx.x;
    float a = w1[idx], b2 = w2[idx];
    #pragma unroll
    for(int b=0;b<Bc;b++){
        g_MW1[b*Ic*Dc + idx] = a;   g_SW1[b*Ic*Dc + idx] = 0.f;
        g_MW2[b*Dc*Ic + idx] = b2;  g_SW2[b*Dc*Ic + idx] = 0.f;
    }
    if(idx < Dc){
        float l = lnw[idx];
        #pragma unroll
        for(int b=0;b<Bc;b++){ g_Mln[b*Dc+idx] = l; g_Sln[b*Dc+idx] = 0.f; }
    }
}

// ---------------- helpers for 32x32 chunk tiles ----------------
__device__ __forceinline__ void st32(float* Ac, float* Bc, int lm, int lk, float4 a, float4 b){
    Ac[(lk+0)*36+lm]=a.x; Ac[(lk+1)*36+lm]=a.y; Ac[(lk+2)*36+lm]=a.z; Ac[(lk+3)*36+lm]=a.w;
    Bc[(lk+0)*36+lm]=b.x; Bc[(lk+1)*36+lm]=b.y; Bc[(lk+2)*36+lm]=b.z; Bc[(lk+3)*36+lm]=b.w;
}
__device__ __forceinline__ void mm32(const float* Ac, const float* Bc, int r, int cb, float acc[4]){
    #pragma unroll
    for(int kk=0;kk<32;kk++){
        float a = Ac[kk*36+r];
        float4 b4 = *(const float4*)&Bc[kk*36+cb];
        acc[0]+=a*b4.x; acc[1]+=a*b4.y; acc[2]+=a*b4.z; acc[3]+=a*b4.w;
    }
}

// ---------------- 128x128 NT tile, 256 threads, double-buffered + depth-2 prefetch ----------------
__device__ __forceinline__ void dev_gemm128(
    const float* __restrict__ Ab, int lda,
    const float* __restrict__ Bb, int ldb,
    float* __restrict__ Cb, int ldc,
    int K, int mode)
{
    __shared__ float As[2][16*132];
    __shared__ float Bs[2][16*132];
    const int tid = threadIdx.x;
    const int ty = tid>>4, tx = tid&15;
    float acc[8][8];
    #pragma unroll
    for(int i=0;i<8;i++){
        #pragma unroll
        for(int j=0;j<8;j++) acc[i][j]=0.f;
    }
    const int lf = tid*2;
    const int m0 = lf>>2,     ka0 = (lf&3)*4;
    const int m1 = (lf+1)>>2, ka1 = ((lf+1)&3)*4;
    const int nkt = K >> 4;   // always even (32 or 64)

    float4 a0A = *(const float4*)&Ab[(long long)m0*lda + ka0];
    float4 a1A = *(const float4*)&Ab[(long long)m1*lda + ka1];
    float4 b0A = *(const float4*)&Bb[(long long)m0*ldb + ka0];
    float4 b1A = *(const float4*)&Bb[(long long)m1*ldb + ka1];
    float4 a0B = *(const float4*)&Ab[(long long)m0*lda + 16 + ka0];
    float4 a1B = *(const float4*)&Ab[(long long)m1*lda + 16 + ka1];
    float4 b0B = *(const float4*)&Bb[(long long)m0*ldb + 16 + ka0];
    float4 b1B = *(const float4*)&Bb[(long long)m1*ldb + 16 + ka1];

    for(int kt=0; kt<nkt; kt+=2){
        // ---- even tile: buffer 0, regs A ----
        {
            float* A0 = As[0]; float* B0 = Bs[0];
            A0[(ka0+0)*132+m0]=a0A.x; A0[(ka0+1)*132+m0]=a0A.y; A0[(ka0+2)*132+m0]=a0A.z; A0[(ka0+3)*132+m0]=a0A.w;
            A0[(ka1+0)*132+m1]=a1A.x; A0[(ka1+1)*132+m1]=a1A.y; A0[(ka1+2)*132+m1]=a1A.z; A0[(ka1+3)*132+m1]=a1A.w;
            B0[(ka0+0)*132+m0]=b0A.x; B0[(ka0+1)*132+m0]=b0A.y; B0[(ka0+2)*132+m0]=b0A.z; B0[(ka0+3)*132+m0]=b0A.w;
            B0[(ka1+0)*132+m1]=b1A.x; B0[(ka1+1)*132+m1]=b1A.y; B0[(ka1+2)*132+m1]=b1A.z; B0[(ka1+3)*132+m1]=b1A.w;
        }
        __syncthreads();
        if(kt+2 < nkt){
            int k0 = (kt+2)*16;
            a0A = *(const float4*)&Ab[(long long)m0*lda + k0 + ka0];
            a1A = *(const float4*)&Ab[(long long)m1*lda + k0 + ka1];
            b0A = *(const float4*)&Bb[(long long)m0*ldb + k0 + ka0];
            b1A = *(const float4*)&Bb[(long long)m1*ldb + k0 + ka1];
        }
        #pragma unroll
        for(int kk=0;kk<16;kk++){
            float4 av0 = *(float4*)&As[0][kk*132 + ty*4];
            float4 av1 = *(float4*)&As[0][kk*132 + 64 + ty*4];
            float4 bv0 = *(float4*)&Bs[0][kk*132 + tx*4];
            float4 bv1 = *(float4*)&Bs[0][kk*132 + 64 + tx*4];
            float av[8] = {av0.x,av0.y,av0.z,av0.w, av1.x,av1.y,av1.z,av1.w};
            float bv[8] = {bv0.x,bv0.y,bv0.z,bv0.w, bv1.x,bv1.y,bv1.z,bv1.w};
            #pragma unroll
            for(int i=0;i<8;i++){
                #pragma unroll
                for(int j=0;j<8;j++) acc[i][j] += av[i]*bv[j];
            }
        }
        // ---- odd tile: buffer 1, regs B ----
        {
            float* A1 = As[1]; float* B1 = Bs[1];
            A1[(ka0+0)*132+m0]=a0B.x; A1[(ka0+1)*132+m0]=a0B.y; A1[(ka0+2)*132+m0]=a0B.z; A1[(ka0+3)*132+m0]=a0B.w;
            A1[(ka1+0)*132+m1]=a1B.x; A1[(ka1+1)*132+m1]=a1B.y; A1[(ka1+2)*132+m1]=a1B.z; A1[(ka1+3)*132+m1]=a1B.w;
            B1[(ka0+0)*132+m0]=b0B.x; B1[(ka0+1)*132+m0]=b0B.y; B1[(ka0+2)*132+m0]=b0B.z; B1[(ka0+3)*132+m0]=b0B.w;
            B1[(ka1+0)*132+m1]=b1B.x; B1[(ka1+1)*132+m1]=b1B.y; B1[(ka1+2)*132+m1]=b1B.z; B1[(ka1+3)*132+m1]=b1B.w;
        }
        __syncthreads();
        if(kt+3 < nkt){
            int k0 = (kt+3)*16;
            a0B = *(const float4*)&Ab[(long long)m0*lda + k0 + ka0];
            a1B = *(const float4*)&Ab[(long long)m1*lda + k0 + ka1];
            b0B = *(const float4*)&Bb[(long long)m0*ldb + k0 + ka0];
            b1B = *(const float4*)&Bb[(long long)m1*ldb + k0 + ka1];
        }
        #pragma unroll
        for(int kk=0;kk<16;kk++){
            float4 av0 = *(float4*)&As[1][kk*132 + ty*4];
            float4 av1 = *(float4*)&As[1][kk*132 + 64 + ty*4];
            float4 bv0 = *(float4*)&Bs[1][kk*132 + tx*4];
            float4 bv1 = *(float4*)&Bs[1][kk*132 + 64 + tx*4];
            float av[8] = {av0.x,av0.y,av0.z,av0.w, av1.x,av1.y,av1.z,av1.w};
            float bv[8] = {bv0.x,bv0.y,bv0.z,bv0.w, bv1.x,bv1.y,bv1.z,bv1.w};
            #pragma unroll
            for(int i=0;i<8;i++){
                #pragma unroll
                for(int j=0;j<8;j++) acc[i][j] += av[i]*bv[j];
            }
        }
    }
    #pragma unroll
    for(int i=0;i<8;i++){
        int row = (i<4) ? (ty*4+i) : (64 + ty*4 + (i-4));
        float c[8];
        #pragma unroll
        for(int j=0;j<8;j++) c[j] = acc[i][j];
        if(mode==1){
            #pragma unroll
            for(int j=0;j<8;j++) c[j] *= sigmoidf(c[j]);
        }
        float4 c0; c0.x=c[0]; c0.y=c[1]; c0.z=c[2]; c0.w=c[3];
        float4 c1; c1.x=c[4]; c1.y=c[5]; c1.z=c[6]; c1.w=c[7];
        *(float4*)&Cb[(long long)row*ldc + tx*4] = c0;
        *(float4*)&Cb[(long long)row*ldc + 64 + tx*4] = c1;
    }
}

__global__ __launch_bounds__(256) void gemm128_gen(
    const float* __restrict__ A, long long sAz, int lda,
    const float* __restrict__ B, long long sBz, int ldb,
    float* __restrict__ C, long long sCz, int ldc,
    int K, int mode)
{
    const float* Ab = A + blockIdx.z*sAz + (long long)blockIdx.y*128*lda;
    const float* Bb = B + blockIdx.z*sBz + (long long)blockIdx.x*128*ldb;
    float* Cb = C + blockIdx.z*sCz + (long long)blockIdx.y*128*ldc + blockIdx.x*128;
    dev_gemm128(Ab, lda, Bb, ldb, Cb, ldc, K, mode);
}

__global__ __launch_bounds__(256) void gemm128_proj(
    const float* __restrict__ x, const float* __restrict__ wk,
    const float* __restrict__ wv, const float* __restrict__ wq)
{
    int w = blockIdx.z;
    const float* W = (w==0)?wk:((w==1)?wv:wq);
    float* dst = (w==0)?g_k:((w==1)?g_v:g_q);
    const float* Ab = x + (long long)blockIdx.y*128*Dc;
    const float* Bb = W + (long long)blockIdx.x*128*Dc;
    float* Cb = dst + (long long)blockIdx.y*128*Dc + blockIdx.x*128;
    dev_gemm128(Ab, Dc, Bb, Dc, Cb, Dc, Dc, 0);
}

// ================= chunk GEMMs: 32x32 tiles, depth-2 prefetch =================
// PA: z/h = silu(Kc @ MW1^T). grid (32 nt, 1, 4 b). K = 512 (16 k-tiles).
__global__ __launch_bounds__(256) void pa_kernel(int ci){
    const int b = blockIdx.z, nt = blockIdx.x;
    const float* A = g_k + ((long long)b*Sc + ci*Cc)*Dc;
    const float* B = g_MW1 + (long long)b*ID + (long long)nt*32*Dc;
    __shared__ float As[2][1152];
    __shared__ float Bs[2][1152];
    const int tid = threadIdx.x;
    const int lm = tid>>3, lk = (tid&7)*4;
    const int r = tid>>3, cb = (tid&7)*4;
    float4 aA = *(const float4*)&A[(long long)lm*Dc + lk];
    float4 bA = *(const float4*)&B[(long long)lm*Dc + lk];
    float4 aB = *(const float4*)&A[(long long)lm*Dc + 32 + lk];
    float4 bB = *(const float4*)&B[(long long)lm*Dc + 32 + lk];
    float acc[4]={0.f,0.f,0.f,0.f};
    for(int kt=0;kt<16;kt+=2){
        st32(As[0], Bs[0], lm, lk, aA, bA);
        __syncthreads();
        if(kt+2<16){
            int k0=(kt+2)*32;
            aA = *(const float4*)&A[(long long)lm*Dc + k0 + lk];
            bA = *(const float4*)&B[(long long)lm*Dc + k0 + lk];
        }
        mm32(As[0], Bs[0], r, cb, acc);
        st32(As[1], Bs[1], lm, lk, aB, bB);
        __syncthreads();
        if(kt+3<16){
            int k0=(kt+3)*32;
            aB = *(const float4*)&A[(long long)lm*Dc + k0 + lk];
            bB = *(const float4*)&B[(long long)lm*Dc + k0 + lk];
        }
        mm32(As[1], Bs[1], r, cb, acc);
    }
    long long idx = (long long)b*CI + (long long)r*Ic + nt*32 + cb;
    float4 z4; z4.x=acc[0]; z4.y=acc[1]; z4.z=acc[2]; z4.w=acc[3];
    *(float4*)&g_z[idx] = z4;
    float4 h4;
    h4.x=acc[0]*sigmoidf(acc[0]); h4.y=acc[1]*sigmoidf(acc[1]);
    h4.z=acc[2]*sigmoidf(acc[2]); h4.w=acc[3]*sigmoidf(acc[3]);
    *(float4*)&g_h[idx] = h4;
}

// PB: o partials = H @ MW2^T. grid (16 nt, 2 ks, 4 b). K=512 per block.
__global__ __launch_bounds__(256) void pb_kernel(){
    const int b = blockIdx.z, nt = blockIdx.x, ks = blockIdx.y;
    const float* A = g_h + (long long)b*CI + ks*512;
    const float* B = g_MW2 + (long long)b*ID + (long long)nt*32*Ic + ks*512;
    __shared__ float As[2][1152];
    __shared__ float Bs[2][1152];
    const int tid = threadIdx.x;
    const int lm = tid>>3, lk = (tid&7)*4;
    const int r = tid>>3, cb = (tid&7)*4;
    float4 aA = *(const float4*)&A[(long long)lm*Ic + lk];
    float4 bA = *(const float4*)&B[(long long)lm*Ic + lk];
    float4 aB = *(const float4*)&A[(long long)lm*Ic + 32 + lk];
    float4 bB = *(const float4*)&B[(long long)lm*Ic + 32 + lk];
    float acc[4]={0.f,0.f,0.f,0.f};
    for(int kt=0;kt<16;kt+=2){
        st32(As[0], Bs[0], lm, lk, aA, bA);
        __syncthreads();
        if(kt+2<16){
            int k0=(kt+2)*32;
            aA = *(const float4*)&A[(long long)lm*Ic + k0 + lk];
            bA = *(const float4*)&B[(long long)lm*Ic + k0 + lk];
        }
        mm32(As[0], Bs[0], r, cb, acc);
        st32(As[1], Bs[1], lm, lk, aB, bB);
        __syncthreads();
        if(kt+3<16){
            int k0=(kt+3)*32;
            aB = *(const float4*)&A[(long long)lm*Ic + k0 + lk];
            bB = *(const float4*)&B[(long long)lm*Ic + k0 + lk];
        }
        mm32(As[1], Bs[1], r, cb, acc);
    }
    float* Cb = g_op + (long long)ks*(Bc*CD) + (long long)b*CD + nt*32;
    float4 o4; o4.x=acc[0]; o4.y=acc[1]; o4.z=acc[2]; o4.w=acc[3];
    *(float4*)&Cb[(long long)r*Dc + cb] = o4;
}

// PD: p = (DO @ MW2) * dsilu(z) + |p|^2 tile partials. grid (32 nt, 1, 4 b). K=512.
__global__ __launch_bounds__(256) void pd_kernel(){
    const int b = blockIdx.z, nt = blockIdx.x;
    const float* A = g_do + (long long)b*CD;
    const float* B = g_MW2 + (long long)b*ID + nt*32;
    __shared__ float As[2][1152];
    __shared__ float Bs[2][1152];
    const int tid = threadIdx.x;
    const int lm = tid>>3, lk = (tid&7)*4;
    const int bk = tid>>3, bnb = (tid&7)*4;
    const int r = tid>>3, cb = (tid&7)*4;
    float4 aA = *(const float4*)&A[(long long)lm*Dc + lk];
    float4 bA = *(const float4*)&B[(long long)bk*Ic + bnb];
    float4 aB = *(const float4*)&A[(long long)lm*Dc + 32 + lk];
    float4 bB = *(const float4*)&B[(long long)(32+bk)*Ic + bnb];
    float acc[4]={0.f,0.f,0.f,0.f};
    for(int kt=0;kt<16;kt+=2){
        {
            float* Ac=As[0]; float* Bc=Bs[0];
            Ac[(lk+0)*36+lm]=aA.x; Ac[(lk+1)*36+lm]=aA.y; Ac[(lk+2)*36+lm]=aA.z; Ac[(lk+3)*36+lm]=aA.w;
            *(float4*)&Bc[bk*36+bnb] = bA;
        }
        __syncthreads();
        if(kt+2<16){
            int k0=(kt+2)*32;
            aA = *(const float4*)&A[(long long)lm*Dc + k0 + lk];
            bA = *(const float4*)&B[(long long)(k0+bk)*Ic + bnb];
        }
        mm32(As[0], Bs[0], r, cb, acc);
        {
            float* Ac=As[1]; float* Bc=Bs[1];
            Ac[(lk+0)*36+lm]=aB.x; Ac[(lk+1)*36+lm]=aB.y; Ac[(lk+2)*36+lm]=aB.z; Ac[(lk+3)*36+lm]=aB.w;
            *(float4*)&Bc[bk*36+bnb] = bB;
        }
        __syncthreads();
        if(kt+3<16){
            int k0=(kt+3)*32;
            aB = *(const float4*)&A[(long long)lm*Dc + k0 + lk];
            bB = *(const float4*)&B[(long long)(k0+bk)*Ic + bnb];
        }
        mm32(As[1], Bs[1], r, cb, acc);
    }
    long long idx = (long long)b*CI + (long long)r*Ic + nt*32 + cb;
    float4 z4 = *(const float4*)&g_z[idx];
    float4 pv;
    { float s=sigmoidf(z4.x); pv.x=acc[0]*(s*(1.f+z4.x*(1.f-s))); }
    { float s=sigmoidf(z4.y); pv.y=acc[1]*(s*(1.f+z4.y*(1.f-s))); }
    { float s=sigmoidf(z4.z); pv.z=acc[2]*(s*(1.f+z4.z*(1.f-s))); }
    { float s=sigmoidf(z4.w); pv.w=acc[3]*(s*(1.f+z4.w*(1.f-s))); }
    *(float4*)&g_p[idx] = pv;
    float sp = pv.x*pv.x + pv.y*pv.y + pv.z*pv.z + pv.w*pv.w;
    sp += __shfl_xor_sync(0xffffffffu, sp, 1);
    sp += __shfl_xor_sync(0xffffffffu, sp, 2);
    sp += __shfl_xor_sync(0xffffffffu, sp, 4);
    if((tid&7)==0) g_npp[(b*Cc+r)*32 + nt] = sp;
}

// ---------------- gates ----------------
__global__ void gates_kernel(const float* __restrict__ x,
                             const float* __restrict__ thw,
                             const float* __restrict__ alw,
                             const float* __restrict__ etw){
    int row = blockIdx.x;
    const float* xr = x + (long long)row*Dc;
    float st=0.f, sa=0.f, se=0.f;
    for(int d=threadIdx.x; d<Dc; d+=128){
        float xv = xr[d];
        st += xv*thw[d]; sa += xv*alw[d]; se += xv*etw[d];
    }
    st = blockReduce(st); sa = blockReduce(sa); se = blockReduce(se);
    if(threadIdx.x == 0){
        g_theta[row] = 0.01f * sigmoidf(st);
        g_alpha[row] = sigmoidf(sa);
        g_eta[row]   = sigmoidf(se);
    }
}

// ---------------- fused activations for k, v, q ----------------
__global__ void act3_kernel(const float* __restrict__ kn, const float* __restrict__ qn){
    int which = blockIdx.x >> 11;
    int row = blockIdx.x & 2047;
    float* buf = (which==0) ? g_k : ((which==1) ? g_v : g_q);
    long long idx = (long long)row*Dc + threadIdx.x;
    float v = buf[idx];
    float sv = v*sigmoidf(v);
    if(which==1){ buf[idx] = sv; return; }
    const float* wnorm = (which==0) ? kn : qn;
    float s2 = blockReduce(sv*sv);
    float n = rsqrtf(s2*(1.f/Dc) + 1e-6f);
    buf[idx] = sv*n*wnorm[threadIdx.x];
}

// ---------------- token backward ----------------
__global__ void token_kernel(int ci){
    int t = blockIdx.x, b = blockIdx.y, d = threadIdx.x;
    int tok = ci*Cc + t;
    long long cidx = ((long long)b*Cc + t)*Dc + d;
    float kv = g_k[((long long)b*Sc + tok)*Dc + d];
    float vv = g_v[((long long)b*Sc + tok)*Dc + d];
    float ov = g_op[cidx] + g_op[(long long)Bc*CD + cidx];
    float ln = g_Mln[b*Dc + d];
    float th = g_theta[b*Sc + tok];
    float s2 = blockReduce(ov*ov);
    float n = rsqrtf(s2*(1.f/Dc) + 1e-6f);
    float y = ln*n*ov;
    float r = kv + y - vv;
    float u = (2.f/Dc)*th*r;
    float gl = u*n*ov;
    float ws = blockReduce(u*ov*ln);
    float dov = n*ln*u - (n*n*n*ov*(1.f/Dc))*ws;
    g_do[cidx] = dov;
    g_gln[cidx] = gl;
    float hv0 = g_h[((long long)b*Cc + t)*Ic + d];
    float hv1 = g_h[((long long)b*Cc + t)*Ic + d + 512];
    float nk = blockReduce(kv*kv);
    float nd = blockReduce(dov*dov);
    float ng = blockReduce(gl*gl);
    float nh = blockReduce(hv0*hv0 + hv1*hv1);
    if(d==0){
        g_nk[b*Cc+t]=nk; g_ndo[b*Cc+t]=nd; g_ngl[b*Cc+t]=ng; g_nh[b*Cc+t]=nh;
    }
    if(t==0){
        __shared__ float sEta[32], sBeta[32];
        if(d < 32){
            sEta[d]  = g_eta[b*Sc + ci*Cc + d];
            sBeta[d] = 1.f - g_alpha[b*Sc + ci*Cc + d];
        }
        __syncthreads();
        if(d==0){
            float E=1.f, F=1.f, c=1.f, cSv=0.f;
            for(int s=Cc-1;s>=0;s--){
                g_sE[b*Cc+s] = E;
                g_sc2[b*Cc+s] = c;
                if(s==0) cSv = sEta[0]*c;
                float Fn = sBeta[s]*F;
                c = Fn + sEta[s]*c;
                E = sEta[s]*E;
                F = Fn;
            }
            g_Ab[b]=E; g_Bpb[b]=F; g_cSb[b]=cSv;
        }
    }
}

// ================= rank updates (64x128 tiles) + ln update, one launch =================
__global__ void __launch_bounds__(256, 2) rank_ln_kernel(int ci){
    const int bid = blockIdx.x, tid = threadIdx.x;
    __shared__ float Ps[32*68];
    __shared__ float Ks[32*132];
    __shared__ float sce[32], scc[32];

    int b;
    const float *P = nullptr, *Kv = nullptr;
    float *Sm = nullptr, *Mm = nullptr;
    int ld = 0, pStr = 0, kStr = 0;
    bool isLn = false;
    if(bid < 256){
        int u = bid; b = u>>6; int tile = u&63;
        int rt = tile>>2, ct = tile&3;
        Sm = g_SW1 + (long long)b*ID + (long long)rt*64*Dc + ct*128;
        Mm = g_MW1 + (long long)b*ID + (long long)rt*64*Dc + ct*128;
        ld = Dc;
        P  = g_p + (long long)b*CI + rt*64;   pStr = Ic;
        Kv = g_k + ((long long)b*Sc + ci*Cc)*Dc + ct*128;  kStr = Dc;
    } else if(bid < 512){
        int u = bid-256; b = u>>6; int tile = u&63;
        int rt = tile>>3, ct = tile&7;
        Sm = g_SW2 + (long long)b*ID + (long long)rt*64*Ic + ct*128;
        Mm = g_MW2 + (long long)b*ID + (long long)rt*64*Ic + ct*128;
        ld = Ic;
        P  = g_do + (long long)b*CD + rt*64;  pStr = Dc;
        Kv = g_h + (long long)b*CI + ct*128;  kStr = Ic;
    } else {
        isLn = true; b = bid-512;
    }

    if(tid < 32){
        float np = 0.f;
        #pragma unroll
        for(int j=0;j<32;j++) np += g_npp[(b*Cc+tid)*32 + j];
        float sq = np*g_nk[b*Cc+tid] + g_ndo[b*Cc+tid]*g_nh[b*Cc+tid] + g_ngl[b*Cc+tid];
        float coef = fminf(1.f/(sqrtf(sq)+1e-6f), 1.f);
        sce[tid] = g_sE[b*Cc+tid]*coef;
        scc[tid] = g_sc2[b*Cc+tid]*coef;
    }

    if(isLn){
        __syncthreads();
        float A = g_Ab[b], Bp = g_Bpb[b], cS = g_cSb[b];
        #pragma unroll
        for(int rep=0;rep<2;rep++){
            int d = tid + rep*256;
            float S = g_Sln[b*Dc+d], M = g_Mln[b*Dc+d];
            float se_=0.f, sc_=0.f;
            #pragma unroll
            for(int t2=0;t2<Cc;t2++){
                float g = g_gln[((long long)b*Cc + t2)*Dc + d];
                se_ += sce[t2]*g;
                sc_ += scc[t2]*g;
            }
            g_Sln[b*Dc+d] = A*S - se_;
            g_Mln[b*Dc+d] = Bp*M + cS*S - sc_;
        }
        return;
    }

    #pragma unroll
    for(int i=0;i<2;i++){
        int f = tid*2 + i;
        int tt = f>>4, cb = (f&15)*4;
        *(float4*)&Ps[tt*68+cb] = *(const float4*)&P[(long long)tt*pStr + cb];
    }
    #pragma unroll
    for(int i=0;i<4;i++){
        int f = tid*4 + i;
        int tt = f>>5, cb = (f&31)*4;
        *(float4*)&Ks[tt*132+cb] = *(const float4*)&Kv[(long long)tt*kStr + cb];
    }
    __syncthreads();

    const int ty = tid>>4, tx = tid&15;
    float ae[4][8], ac[4][8];
    #pragma unroll
    for(int i=0;i<4;i++){
        #pragma unroll
        for(int j=0;j<8;j++){ ae[i][j]=0.f; ac[i][j]=0.f; }
    }
    #pragma unroll
    for(int t=0;t<32;t++){
        float ce = sce[t], cc = scc[t];
        float4 p4 = *(float4*)&Ps[t*68 + ty*4];
        float4 ka = *(float4*)&Ks[t*132 + tx*8];
        float4 kb = *(float4*)&Ks[t*132 + tx*8 + 4];
        float pv[4] = {p4.x, p4.y, p4.z, p4.w};
        float kv8[8] = {ka.x,ka.y,ka.z,ka.w, kb.x,kb.y,kb.z,kb.w};
        #pragma unroll
        for(int i=0;i<4;i++){
            float pe = ce*pv[i], pc = cc*pv[i];
            #pragma unroll
            for(int j=0;j<8;j++){
                ae[i][j] += pe*kv8[j];
                ac[i][j] += pc*kv8[j];
            }
        }
    }
    float A = g_Ab[b], Bp = g_Bpb[b], cS = g_cSb[b];
    #pragma unroll
    for(int i=0;i<4;i++){
        long long base = (long long)(ty*4+i)*ld + tx*8;
        #pragma unroll
        for(int half=0;half<2;half++){
            float4 s4 = *(float4*)&Sm[base + half*4];
            float4 m4 = *(float4*)&Mm[base + half*4];
            float4 ns, nm;
            int j0 = half*4;
            ns.x = A*s4.x - ae[i][j0+0]; nm.x = Bp*m4.x + cS*s4.x - ac[i][j0+0];
            ns.y = A*s4.y - ae[i][j0+1]; nm.y = Bp*m4.y + cS*s4.y - ac[i][j0+1];
            ns.z = A*s4.z - ae[i][j0+2]; nm.z = Bp*m4.z + cS*s4.z - ac[i][j0+2];
            ns.w = A*s4.w - ae[i][j0+3]; nm.w = Bp*m4.w + cS*s4.w - ac[i][j0+3];
            *(float4*)&Sm[base + half*4] = ns;
            *(float4*)&Mm[base + half*4] = nm;
        }
    }
}

// ---------------- final combine ----------------
__global__ void final_kernel(float* __restrict__ out){
    int row = blockIdx.x, d = threadIdx.x;
    int b = row >> 9;
    long long idx = (long long)row*Dc + d;
    float qv = g_q[idx];
    float ov = g_obuf[idx];
    float ln = g_Mln[b*Dc + d];
    float s2 = blockReduce(ov*ov);
    float n = rsqrtf(s2*(1.f/Dc) + 1e-6f);
    out[idx] = qv + ov*n*ln;
}

extern "C" void kernel_launch(void* const* d_in, const int* in_sizes, int n_in,
                              void* d_out, int out_size){
    const float* x   = (const float*)d_in[0];
    const float* wq  = (const float*)d_in[1];
    const float* wk  = (const float*)d_in[2];
    const float* wv  = (const float*)d_in[3];
    const float* qn  = (const float*)d_in[4];
    const float* kn  = (const float*)d_in[5];
    const float* alw = (const float*)d_in[6];
    const float* thw = (const float*)d_in[7];
    const float* etw = (const float*)d_in[8];
    const float* w1  = (const float*)d_in[9];
    const float* w2  = (const float*)d_in[10];
    const float* lnw = (const float*)d_in[11];
    float* out = (float*)d_out;

    float *q_, *mw1_, *mw2_, *hbuf_, *obuf_;
    cudaGetSymbolAddress((void**)&q_, g_q);
    cudaGetSymbolAddress((void**)&mw1_, g_MW1);
    cudaGetSymbolAddress((void**)&mw2_, g_MW2);
    cudaGetSymbolAddress((void**)&hbuf_, g_hbuf);
    cudaGetSymbolAddress((void**)&obuf_, g_obuf);

    init_kernel<<<ID/256, 256>>>(w1, w2, lnw);

    gemm128_proj<<<dim3(4, 16, 3), 256>>>(x, wk, wv, wq);
    gates_kernel<<<Bc*Sc, 128>>>(x, thw, alw, etw);
    act3_kernel<<<3*Bc*Sc, Dc>>>(kn, qn);

    for(int ci=0; ci<NCc; ci++){
        pa_kernel<<<dim3(32,1,4), 256>>>(ci);
        pb_kernel<<<dim3(16,2,4), 256>>>();
        token_kernel<<<dim3(Cc, Bc), Dc>>>(ci);
        pd_kernel<<<dim3(32,1,4), 256>>>();
        rank_ln_kernel<<<516, 256>>>(ci);
    }

    gemm128_gen<<<dim3(8, 4, 4), 256>>>(q_, SD, Dc, mw1_, ID, Dc, hbuf_, SI, Ic, 512, 1);
    gemm128_gen<<<dim3(4, 4, 4), 256>>>(hbuf_, SI, Ic, mw2_, ID, Ic, obuf_, SD, Dc, 1024, 0);
    final_kernel<<<Bc*Sc, Dc>>>(out);
}